// round 10
// baseline (speedup 1.0000x reference)
#include <cuda_runtime.h>
#include <cuda_fp16.h>
#include <cstdint>
#include <math.h>

// ---------------------------------------------------------------------------
// Portable tensor-core path: mma.sync + ldmatrix (no sm_103a-gated PTX).
// Round 9: L1-wavefront diet.
//  - feat: coalesced float4 LDG -> fp16 STS (conflict-free) -> ldmatrix.x4
//  - head weight columns permuted so each thread owns a contiguous rgb quad
//    -> epilogue is 4 coalesced STG.128 (+ sigma), no scatter, no staging.
//  - M=32/warp, B-fragments amortized over 2 tiles, 4 CTAs/SM.
// ---------------------------------------------------------------------------

#define LDSM_X4(r0, r1, r2, r3, addr) \
    asm volatile("ldmatrix.sync.aligned.m8n8.x4.shared.b16 {%0,%1,%2,%3}, [%4];" \
                 : "=r"(r0), "=r"(r1), "=r"(r2), "=r"(r3) : "r"(addr))

#define LDSM_X2(r0, r1, addr) \
    asm volatile("ldmatrix.sync.aligned.m8n8.x2.shared.b16 {%0,%1}, [%2];" \
                 : "=r"(r0), "=r"(r1) : "r"(addr))

#define MMA16816(c, a0, a1, a2, a3, b0, b1) \
    asm volatile("mma.sync.aligned.m16n8k16.row.col.f32.f16.f16.f32 " \
                 "{%0,%1,%2,%3}, {%4,%5,%6,%7}, {%8,%9}, {%0,%1,%2,%3};" \
                 : "+f"((c)[0]), "+f"((c)[1]), "+f"((c)[2]), "+f"((c)[3]) \
                 : "r"(a0), "r"(a1), "r"(a2), "r"(a3), "r"(b0), "r"(b1))

namespace {

__device__ __forceinline__ uint32_t smem_u32(const void* p) {
    uint32_t a;
    asm("{ .reg .u64 t; cvta.to.shared.u64 t, %1; cvt.u32.u64 %0, t; }"
        : "=r"(a) : "l"(p));
    return a;
}

__device__ __forceinline__ uint32_t pack_f16x2(float lo, float hi) {
    uint32_t r;
    asm("cvt.rn.f16x2.f32 %0, %1, %2;" : "=r"(r) : "f"(hi), "f"(lo));
    return r;
}

__device__ __forceinline__ uint32_t pack_relu2(float lo, float hi) {
    uint32_t r = pack_f16x2(lo, hi);
    asm("max.f16x2 %0, %0, %1;" : "+r"(r) : "r"(0u));
    return r;
}

__device__ __forceinline__ float2 lds64(uint32_t addr) {
    float2 r;
    asm volatile("ld.shared.v2.f32 {%0,%1}, [%2];"
                 : "=f"(r.x), "=f"(r.y) : "r"(addr));
    return r;
}

__device__ __forceinline__ float softplus_dev(float s) {
    return (s > 20.0f) ? s : log1pf(expf(s));
}

constexpr int WSTR = 72;   // weight smem row stride (halfs), ldmatrix-safe
constexpr int FSTR = 40;   // feat smem row stride (halfs): 80B, 20r%32 distinct
constexpr int NCTA = 2048;
constexpr int CTA_THREADS = 128;

__global__ void __launch_bounds__(128, 4) ngp_mlp_kernel(
    const float* __restrict__ feat,
    const float* __restrict__ W0, const float* __restrict__ b0,
    const float* __restrict__ W1, const float* __restrict__ b1,
    const float* __restrict__ Ws, const float* __restrict__ bs,
    const float* __restrict__ Wr, const float* __restrict__ br,
    float* __restrict__ sigma_out, float* __restrict__ rgb_out,
    int rows_per_cta)
{
    __shared__ __half w0t[64 * WSTR];      // [n<64][k<32]
    __shared__ __half w1t[64 * WSTR];      // [n<64][k<64]
    __shared__ __half w2t[24 * WSTR];      // permuted head: h<16 rgb, h=16 sigma
    __shared__ float  sbias[152];          // b0 | b1 | permuted head bias
    __shared__ __half act[4][32 * FSTR];   // per-warp feat staging (K=32)

    const int tid  = threadIdx.x;
    const int wid  = tid >> 5;
    const int lane = tid & 31;

    // ---- stage weights: fp32 gmem [K][N] -> fp16 smem [N][K] ----
    for (int i = tid; i < 32 * 64; i += CTA_THREADS) {
        int k = i >> 6, n = i & 63;
        w0t[n * WSTR + k] = __float2half(W0[i]);
    }
    for (int i = tid; i < 64 * 64; i += CTA_THREADS) {
        int k = i >> 6, n = i & 63;
        w1t[n * WSTR + k] = __float2half(W1[i]);
    }
    for (int i = tid; i < 24 * WSTR; i += CTA_THREADS)
        w2t[i] = __float2half(0.0f);
    if (tid < 64) { sbias[tid] = b0[tid]; sbias[64 + tid] = b1[tid]; }
    if (tid < 24) {
        // permuted head bias: position h<16 <- br[g], h==16 <- bs-1
        float v = 0.0f;
        if (tid == 16) v = bs[0] - 1.0f;
        else if (tid < 16) {
            int n = tid >> 3, c = (tid >> 1) & 3, j = tid & 1;
            v = br[4 * c + 2 * n + j];
        }
        sbias[128 + tid] = v;
    }
    __syncthreads();
    if (tid < 64)
        w2t[16 * WSTR + tid] = __float2half(Ws[tid]);   // sigma at head col 16
    for (int i = tid; i < 64 * 16; i += CTA_THREADS) {   // rgb col g -> pos h
        int k = i >> 4, g = i & 15;
        int h = ((g >> 1) & 1) * 8 + (g >> 2) * 2 + (g & 1);
        w2t[h * WSTR + k] = __float2half(Wr[i]);
    }
    __syncthreads();

    // ---- addressing ----
    const uint32_t w0b = smem_u32(w0t), w1b = smem_u32(w1t), w2b = smem_u32(w2t);
    const uint32_t sb  = smem_u32(sbias);
    const uint32_t acb = smem_u32(&act[wid][0]);
    const int l15  = lane & 15;
    const int col2 = (lane & 3) * 2;
    const int cq   = lane & 3;

    const uint32_t bl4 = (uint32_t)((((lane >> 4) & 1) * 8 + (lane & 7)) * (WSTR * 2)
                                    + ((lane >> 3) & 1) * 16);
    const uint32_t bl2 = (uint32_t)((l15 & 7) * (WSTR * 2) + ((l15 >> 3) & 1) * 16);

    // feat A-fragment ldmatrix: tile t rows t*16+l15, k-half, kt*16 cols
    const uint32_t fl = (uint32_t)(l15 * (FSTR * 2) + ((lane >> 4) & 1) * 16);

    const int ep_row = lane >> 2;      // fragment row within tile
    const int fq_r   = lane >> 3;      // coalesced feat load: row within quad
    const int fq_c   = lane & 7;       // float4 column

    const uint32_t sb0 = sb + (uint32_t)col2 * 4;
    const uint32_t sb1 = sb0 + 256;
    const uint32_t sbh = sb0 + 512;

    const int cta_base = blockIdx.x * rows_per_cta;
    const float4* f4 = (const float4*)feat;

    // ---- prime: load + stage iter-0 feat ----
    float4 v[8];
    {
        size_t rbase = (size_t)(cta_base + wid * 32);
        #pragma unroll
        for (int q = 0; q < 8; q++)
            v[q] = f4[(rbase + 4 * q + fq_r) * 8 + fq_c];
        #pragma unroll
        for (int q = 0; q < 8; q++) {
            uint2 u;
            u.x = pack_f16x2(v[q].x, v[q].y);
            u.y = pack_f16x2(v[q].z, v[q].w);
            *(uint2*)&act[wid][(4 * q + fq_r) * FSTR + fq_c * 4] = u;
        }
    }
    __syncwarp();

    #pragma unroll 1
    for (int it = 0; it < rows_per_cta; it += 128) {
        const int warp_r0 = cta_base + it + wid * 32;

        // -- layer-0 A fragments from staged feat --
        uint32_t A0[2][2][4];
        #pragma unroll
        for (int t = 0; t < 2; t++)
            #pragma unroll
            for (int kt = 0; kt < 2; kt++)
                LDSM_X4(A0[t][kt][0], A0[t][kt][1], A0[t][kt][2], A0[t][kt][3],
                        acb + fl + (uint32_t)t * (16 * FSTR * 2) + kt * 32);

        // -- layer 0: [32,32] @ W0 --
        float c[2][8][4];
        #pragma unroll
        for (int nt = 0; nt < 8; nt++) {
            float2 bv = lds64(sb0 + (uint32_t)nt * 32);
            #pragma unroll
            for (int t = 0; t < 2; t++) {
                c[t][nt][0] = bv.x; c[t][nt][1] = bv.y;
                c[t][nt][2] = bv.x; c[t][nt][3] = bv.y;
            }
        }
        #pragma unroll
        for (int kt = 0; kt < 2; kt++)
            #pragma unroll
            for (int np = 0; np < 8; np += 2) {
                uint32_t b0r, b1r, b2r, b3r;
                LDSM_X4(b0r, b1r, b2r, b3r,
                        w0b + bl4 + (uint32_t)np * (8 * WSTR * 2) + kt * 32);
                #pragma unroll
                for (int t = 0; t < 2; t++) {
                    MMA16816(c[t][np],     A0[t][kt][0], A0[t][kt][1],
                             A0[t][kt][2], A0[t][kt][3], b0r, b1r);
                    MMA16816(c[t][np + 1], A0[t][kt][0], A0[t][kt][1],
                             A0[t][kt][2], A0[t][kt][3], b2r, b3r);
                }
            }

        // -- repack C -> A (relu fused) --
        uint32_t A1[2][4][4];
        #pragma unroll
        for (int t = 0; t < 2; t++)
            #pragma unroll
            for (int kt = 0; kt < 4; kt++) {
                A1[t][kt][0] = pack_relu2(c[t][2 * kt][0],     c[t][2 * kt][1]);
                A1[t][kt][1] = pack_relu2(c[t][2 * kt][2],     c[t][2 * kt][3]);
                A1[t][kt][2] = pack_relu2(c[t][2 * kt + 1][0], c[t][2 * kt + 1][1]);
                A1[t][kt][3] = pack_relu2(c[t][2 * kt + 1][2], c[t][2 * kt + 1][3]);
            }

        // -- layer 1: [32,64] @ W1 --
        #pragma unroll
        for (int nt = 0; nt < 8; nt++) {
            float2 bv = lds64(sb1 + (uint32_t)nt * 32);
            #pragma unroll
            for (int t = 0; t < 2; t++) {
                c[t][nt][0] = bv.x; c[t][nt][1] = bv.y;
                c[t][nt][2] = bv.x; c[t][nt][3] = bv.y;
            }
        }
        #pragma unroll
        for (int kt = 0; kt < 4; kt++)
            #pragma unroll
            for (int np = 0; np < 8; np += 2) {
                uint32_t b0r, b1r, b2r, b3r;
                LDSM_X4(b0r, b1r, b2r, b3r,
                        w1b + bl4 + (uint32_t)np * (8 * WSTR * 2) + kt * 32);
                #pragma unroll
                for (int t = 0; t < 2; t++) {
                    MMA16816(c[t][np],     A1[t][kt][0], A1[t][kt][1],
                             A1[t][kt][2], A1[t][kt][3], b0r, b1r);
                    MMA16816(c[t][np + 1], A1[t][kt][0], A1[t][kt][1],
                             A1[t][kt][2], A1[t][kt][3], b2r, b3r);
                }
            }

        // -- late coalesced prefetch of next iter's feat --
        {
            const int itn = (it + 128 < rows_per_cta) ? it + 128 : it;
            size_t rbase = (size_t)(cta_base + itn + wid * 32);
            #pragma unroll
            for (int q = 0; q < 8; q++)
                v[q] = f4[(rbase + 4 * q + fq_r) * 8 + fq_c];
        }

        // -- repack again --
        #pragma unroll
        for (int t = 0; t < 2; t++)
            #pragma unroll
            for (int kt = 0; kt < 4; kt++) {
                A1[t][kt][0] = pack_relu2(c[t][2 * kt][0],     c[t][2 * kt][1]);
                A1[t][kt][1] = pack_relu2(c[t][2 * kt][2],     c[t][2 * kt][3]);
                A1[t][kt][2] = pack_relu2(c[t][2 * kt + 1][0], c[t][2 * kt + 1][1]);
                A1[t][kt][3] = pack_relu2(c[t][2 * kt + 1][2], c[t][2 * kt + 1][3]);
            }

        // -- heads (permuted): [32,64] @ W2 -> thread owns rgb quad --
        float ch[2][3][4];
        #pragma unroll
        for (int nt = 0; nt < 3; nt++) {
            float2 bv = lds64(sbh + (uint32_t)nt * 32);
            #pragma unroll
            for (int t = 0; t < 2; t++) {
                ch[t][nt][0] = bv.x; ch[t][nt][1] = bv.y;
                ch[t][nt][2] = bv.x; ch[t][nt][3] = bv.y;
            }
        }
        #pragma unroll
        for (int kt = 0; kt < 4; kt++) {
            uint32_t b0r, b1r, b2r, b3r;
            LDSM_X4(b0r, b1r, b2r, b3r, w2b + bl4 + kt * 32);
            uint32_t d0r, d1r;
            LDSM_X2(d0r, d1r, w2b + bl2 + (uint32_t)(16 * WSTR * 2) + kt * 32);
            #pragma unroll
            for (int t = 0; t < 2; t++) {
                MMA16816(ch[t][0], A1[t][kt][0], A1[t][kt][1],
                         A1[t][kt][2], A1[t][kt][3], b0r, b1r);
                MMA16816(ch[t][1], A1[t][kt][0], A1[t][kt][1],
                         A1[t][kt][2], A1[t][kt][3], b2r, b3r);
                MMA16816(ch[t][2], A1[t][kt][0], A1[t][kt][1],
                         A1[t][kt][2], A1[t][kt][3], d0r, d1r);
            }
        }

        // -- epilogue: fully coalesced stores --
        #pragma unroll
        for (int t = 0; t < 2; t++) {
            const int gr0 = warp_r0 + t * 16 + ep_row;
            const int gr1 = gr0 + 8;
            // thread owns rgb cols 4cq..4cq+3 (head permutation)
            *(float4*)(rgb_out + (size_t)gr0 * 16 + 4 * cq) =
                make_float4(ch[t][0][0], ch[t][0][1], ch[t][1][0], ch[t][1][1]);
            *(float4*)(rgb_out + (size_t)gr1 * 16 + 4 * cq) =
                make_float4(ch[t][0][2], ch[t][0][3], ch[t][1][2], ch[t][1][3]);
            if (cq == 0) {
                sigma_out[gr0] = softplus_dev(ch[t][2][0]);
                sigma_out[gr1] = softplus_dev(ch[t][2][2]);
            }
        }

        // -- stage prefetched feat for next iteration --
        #pragma unroll
        for (int q = 0; q < 8; q++) {
            uint2 u;
            u.x = pack_f16x2(v[q].x, v[q].y);
            u.y = pack_f16x2(v[q].z, v[q].w);
            *(uint2*)&act[wid][(4 * q + fq_r) * FSTR + fq_c * 4] = u;
        }
        __syncwarp();
    }
}

}  // namespace

extern "C" void kernel_launch(void* const* d_in, const int* in_sizes, int n_in,
                              void* d_out, int out_size) {
    const float* feat = (const float*)d_in[0];
    const float* W0   = (const float*)d_in[1];
    const float* b0   = (const float*)d_in[2];
    const float* W1   = (const float*)d_in[3];
    const float* b1   = (const float*)d_in[4];
    const float* Ws   = (const float*)d_in[5];
    const float* bs   = (const float*)d_in[6];
    const float* Wr   = (const float*)d_in[7];
    const float* br   = (const float*)d_in[8];

    float* out = (float*)d_out;
    const int Bn = in_sizes[0] / 32;           // rows (2^21)
    float* sigma = out;                         // [B]
    float* rgb   = out + Bn;                    // [B,16]

    const int rpc = Bn / NCTA;                  // 1024
    ngp_mlp_kernel<<<NCTA, CTA_THREADS>>>(feat, W0, b0, W1, b1, Ws, bs, Wr, br,
                                          sigma, rgb, rpc);
}

// round 11
// speedup vs baseline: 1.3369x; 1.3369x over previous
#include <cuda_runtime.h>
#include <cuda_fp16.h>
#include <cstdint>
#include <math.h>

// ---------------------------------------------------------------------------
// Portable tensor-core path: mma.sync + ldmatrix (no sm_103a-gated PTX).
// Round 11: R8 base (direct-to-fragment feat LDG, late prefetch, 4 CTAs/SM)
// + permuted head weights so the epilogue is coalesced STG.128.
// ---------------------------------------------------------------------------

#define LDSM_X4(r0, r1, r2, r3, addr) \
    asm volatile("ldmatrix.sync.aligned.m8n8.x4.shared.b16 {%0,%1,%2,%3}, [%4];" \
                 : "=r"(r0), "=r"(r1), "=r"(r2), "=r"(r3) : "r"(addr))

#define LDSM_X2(r0, r1, addr) \
    asm volatile("ldmatrix.sync.aligned.m8n8.x2.shared.b16 {%0,%1}, [%2];" \
                 : "=r"(r0), "=r"(r1) : "r"(addr))

#define MMA16816(c, a0, a1, a2, a3, b0, b1) \
    asm volatile("mma.sync.aligned.m16n8k16.row.col.f32.f16.f16.f32 " \
                 "{%0,%1,%2,%3}, {%4,%5,%6,%7}, {%8,%9}, {%0,%1,%2,%3};" \
                 : "+f"((c)[0]), "+f"((c)[1]), "+f"((c)[2]), "+f"((c)[3]) \
                 : "r"(a0), "r"(a1), "r"(a2), "r"(a3), "r"(b0), "r"(b1))

namespace {

__device__ __forceinline__ uint32_t smem_u32(const void* p) {
    uint32_t a;
    asm("{ .reg .u64 t; cvta.to.shared.u64 t, %1; cvt.u32.u64 %0, t; }"
        : "=r"(a) : "l"(p));
    return a;
}

__device__ __forceinline__ uint32_t pack_f16x2(float lo, float hi) {
    uint32_t r;
    asm("cvt.rn.f16x2.f32 %0, %1, %2;" : "=r"(r) : "f"(hi), "f"(lo));
    return r;
}

__device__ __forceinline__ uint32_t pack_relu2(float lo, float hi) {
    uint32_t r = pack_f16x2(lo, hi);
    asm("max.f16x2 %0, %0, %1;" : "+r"(r) : "r"(0u));
    return r;
}

__device__ __forceinline__ float2 lds64(uint32_t addr) {
    float2 r;
    asm volatile("ld.shared.v2.f32 {%0,%1}, [%2];"
                 : "=f"(r.x), "=f"(r.y) : "r"(addr));
    return r;
}

__device__ __forceinline__ float softplus_dev(float s) {
    return (s > 20.0f) ? s : log1pf(expf(s));
}

constexpr int WSTR = 72;     // halfs per SMEM row (144B) -> ldmatrix conflict-free
constexpr int NCTA = 2048;
constexpr int CTA_THREADS = 128;

__global__ void __launch_bounds__(128, 4) ngp_mlp_kernel(
    const float* __restrict__ feat,
    const float* __restrict__ W0, const float* __restrict__ b0,
    const float* __restrict__ W1, const float* __restrict__ b1,
    const float* __restrict__ Ws, const float* __restrict__ bs,
    const float* __restrict__ Wr, const float* __restrict__ br,
    float* __restrict__ sigma_out, float* __restrict__ rgb_out,
    int rows_per_cta)
{
    __shared__ __half w0t[64 * WSTR];      // [n<64][k<32] fp16, transposed
    __shared__ __half w1t[64 * WSTR];      // [n<64][k<64]
    __shared__ __half w2t[24 * WSTR];      // permuted head: h<16 rgb, h=16 sigma
    __shared__ float  sbias[152];          // b0 | b1 | permuted head bias

    const int tid  = threadIdx.x;
    const int wid  = tid >> 5;
    const int lane = tid & 31;

    // ---- stage weights: fp32 gmem [K][N] -> fp16 smem [N][K] ----
    for (int i = tid; i < 32 * 64; i += CTA_THREADS) {
        int k = i >> 6, n = i & 63;
        w0t[n * WSTR + k] = __float2half(W0[i]);
    }
    for (int i = tid; i < 64 * 64; i += CTA_THREADS) {
        int k = i >> 6, n = i & 63;
        w1t[n * WSTR + k] = __float2half(W1[i]);
    }
    for (int i = tid; i < 24 * WSTR; i += CTA_THREADS)
        w2t[i] = __float2half(0.0f);
    if (tid < 64) { sbias[tid] = b0[tid]; sbias[64 + tid] = b1[tid]; }
    if (tid < 24) {
        // permuted head bias: position h<16 <- br[4c+2n+j], h==16 <- bs-1
        float v = 0.0f;
        if (tid == 16) v = bs[0] - 1.0f;
        else if (tid < 16) {
            int n = tid >> 3, c = (tid >> 1) & 3, j = tid & 1;
            v = br[4 * c + 2 * n + j];
        }
        sbias[128 + tid] = v;
    }
    __syncthreads();
    if (tid < 64)
        w2t[16 * WSTR + tid] = __float2half(Ws[tid]);   // sigma at head col 16
    for (int i = tid; i < 64 * 16; i += CTA_THREADS) {   // rgb col g -> pos h
        int k = i >> 4, g = i & 15;
        int h = ((g >> 1) & 1) * 8 + (g >> 2) * 2 + (g & 1);
        w2t[h * WSTR + k] = __float2half(Wr[i]);
    }
    __syncthreads();

    // ---- addressing ----
    const uint32_t w0b = smem_u32(w0t), w1b = smem_u32(w1t), w2b = smem_u32(w2t);
    const uint32_t sb  = smem_u32(sbias);
    const int l15  = lane & 15;
    const int col2 = (lane & 3) * 2;
    const int cq   = lane & 3;

    const uint32_t bl4 = (uint32_t)((((lane >> 4) & 1) * 8 + (lane & 7)) * (WSTR * 2)
                                    + ((lane >> 3) & 1) * 16);
    const uint32_t bl2 = (uint32_t)((l15 & 7) * (WSTR * 2) + ((l15 >> 3) & 1) * 16);

    const int ep_row   = lane >> 2;          // A-fragment row within tile

    const uint32_t sb0 = sb + (uint32_t)col2 * 4;        // b0
    const uint32_t sb1 = sb0 + 256;                      // b1
    const uint32_t sbh = sb0 + 512;                      // head

    const int cta_base = blockIdx.x * rows_per_cta;
    const float2* f2 = (const float2*)feat;

    // prime pipeline: feat for iter 0 in fragment layout
    float2 vf[2][2][4];
    {
        size_t base = (size_t)(cta_base + wid * 32 + ep_row) * 16 + cq;
        #pragma unroll
        for (int t = 0; t < 2; t++)
            #pragma unroll
            for (int h = 0; h < 2; h++)
                #pragma unroll
                for (int o = 0; o < 4; o++)
                    vf[t][h][o] = f2[base + (size_t)(t * 16 + h * 8) * 16 + o * 4];
    }

    #pragma unroll 1
    for (int it = 0; it < rows_per_cta; it += 128) {
        const int warp_r0 = cta_base + it + wid * 32;

        // -- convert prefetched feat to layer-0 A fragments (vf dies here) --
        uint32_t A0[2][2][4];
        #pragma unroll
        for (int t = 0; t < 2; t++)
            #pragma unroll
            for (int o = 0; o < 4; o++)
                #pragma unroll
                for (int h = 0; h < 2; h++)
                    A0[t][o >> 1][(o & 1) * 2 + h] =
                        pack_f16x2(vf[t][h][o].x, vf[t][h][o].y);

        // -- layer 0: [32,32] @ W0; each B-fragment feeds both tiles --
        float c[2][8][4];
        #pragma unroll
        for (int nt = 0; nt < 8; nt++) {
            float2 bv = lds64(sb0 + (uint32_t)nt * 32);
            #pragma unroll
            for (int t = 0; t < 2; t++) {
                c[t][nt][0] = bv.x; c[t][nt][1] = bv.y;
                c[t][nt][2] = bv.x; c[t][nt][3] = bv.y;
            }
        }
        #pragma unroll
        for (int kt = 0; kt < 2; kt++)
            #pragma unroll
            for (int np = 0; np < 8; np += 2) {
                uint32_t b0r, b1r, b2r, b3r;
                LDSM_X4(b0r, b1r, b2r, b3r,
                        w0b + bl4 + (uint32_t)np * (8 * WSTR * 2) + kt * 32);
                #pragma unroll
                for (int t = 0; t < 2; t++) {
                    MMA16816(c[t][np],     A0[t][kt][0], A0[t][kt][1],
                             A0[t][kt][2], A0[t][kt][3], b0r, b1r);
                    MMA16816(c[t][np + 1], A0[t][kt][0], A0[t][kt][1],
                             A0[t][kt][2], A0[t][kt][3], b2r, b3r);
                }
            }

        // -- repack C -> A (relu fused) --
        uint32_t A1[2][4][4];
        #pragma unroll
        for (int t = 0; t < 2; t++)
            #pragma unroll
            for (int kt = 0; kt < 4; kt++) {
                A1[t][kt][0] = pack_relu2(c[t][2 * kt][0],     c[t][2 * kt][1]);
                A1[t][kt][1] = pack_relu2(c[t][2 * kt][2],     c[t][2 * kt][3]);
                A1[t][kt][2] = pack_relu2(c[t][2 * kt + 1][0], c[t][2 * kt + 1][1]);
                A1[t][kt][3] = pack_relu2(c[t][2 * kt + 1][2], c[t][2 * kt + 1][3]);
            }

        // -- layer 1: [32,64] @ W1 --
        #pragma unroll
        for (int nt = 0; nt < 8; nt++) {
            float2 bv = lds64(sb1 + (uint32_t)nt * 32);
            #pragma unroll
            for (int t = 0; t < 2; t++) {
                c[t][nt][0] = bv.x; c[t][nt][1] = bv.y;
                c[t][nt][2] = bv.x; c[t][nt][3] = bv.y;
            }
        }
        #pragma unroll
        for (int kt = 0; kt < 4; kt++)
            #pragma unroll
            for (int np = 0; np < 8; np += 2) {
                uint32_t b0r, b1r, b2r, b3r;
                LDSM_X4(b0r, b1r, b2r, b3r,
                        w1b + bl4 + (uint32_t)np * (8 * WSTR * 2) + kt * 32);
                #pragma unroll
                for (int t = 0; t < 2; t++) {
                    MMA16816(c[t][np],     A1[t][kt][0], A1[t][kt][1],
                             A1[t][kt][2], A1[t][kt][3], b0r, b1r);
                    MMA16816(c[t][np + 1], A1[t][kt][0], A1[t][kt][1],
                             A1[t][kt][2], A1[t][kt][3], b2r, b3r);
                }
            }

        // -- LATE prefetch of next iteration's feat (vf live only from here) --
        {
            const int itn = (it + 128 < rows_per_cta) ? it + 128 : it;
            size_t base = (size_t)(cta_base + itn + wid * 32 + ep_row) * 16 + cq;
            #pragma unroll
            for (int t = 0; t < 2; t++)
                #pragma unroll
                for (int h = 0; h < 2; h++)
                    #pragma unroll
                    for (int o = 0; o < 4; o++)
                        vf[t][h][o] = f2[base + (size_t)(t * 16 + h * 8) * 16 + o * 4];
        }

        // -- repack again (reuse A1 storage) --
        #pragma unroll
        for (int t = 0; t < 2; t++)
            #pragma unroll
            for (int kt = 0; kt < 4; kt++) {
                A1[t][kt][0] = pack_relu2(c[t][2 * kt][0],     c[t][2 * kt][1]);
                A1[t][kt][1] = pack_relu2(c[t][2 * kt][2],     c[t][2 * kt][3]);
                A1[t][kt][2] = pack_relu2(c[t][2 * kt + 1][0], c[t][2 * kt + 1][1]);
                A1[t][kt][3] = pack_relu2(c[t][2 * kt + 1][2], c[t][2 * kt + 1][3]);
            }

        // -- heads (permuted): [32,64] @ W2 -> thread owns rgb quad --
        float ch[2][3][4];
        #pragma unroll
        for (int nt = 0; nt < 3; nt++) {
            float2 bv = lds64(sbh + (uint32_t)nt * 32);
            #pragma unroll
            for (int t = 0; t < 2; t++) {
                ch[t][nt][0] = bv.x; ch[t][nt][1] = bv.y;
                ch[t][nt][2] = bv.x; ch[t][nt][3] = bv.y;
            }
        }
        #pragma unroll
        for (int kt = 0; kt < 4; kt++) {
            uint32_t b0r, b1r, b2r, b3r;
            LDSM_X4(b0r, b1r, b2r, b3r, w2b + bl4 + kt * 32);
            uint32_t d0r, d1r;
            LDSM_X2(d0r, d1r, w2b + bl2 + (uint32_t)(16 * WSTR * 2) + kt * 32);
            #pragma unroll
            for (int t = 0; t < 2; t++) {
                MMA16816(ch[t][0], A1[t][kt][0], A1[t][kt][1],
                         A1[t][kt][2], A1[t][kt][3], b0r, b1r);
                MMA16816(ch[t][1], A1[t][kt][0], A1[t][kt][1],
                         A1[t][kt][2], A1[t][kt][3], b2r, b3r);
                MMA16816(ch[t][2], A1[t][kt][0], A1[t][kt][1],
                         A1[t][kt][2], A1[t][kt][3], d0r, d1r);
            }
        }

        // -- epilogue: fully coalesced stores --
        #pragma unroll
        for (int t = 0; t < 2; t++) {
            const int gr0 = warp_r0 + t * 16 + ep_row;
            const int gr1 = gr0 + 8;
            *(float4*)(rgb_out + (size_t)gr0 * 16 + 4 * cq) =
                make_float4(ch[t][0][0], ch[t][0][1], ch[t][1][0], ch[t][1][1]);
            *(float4*)(rgb_out + (size_t)gr1 * 16 + 4 * cq) =
                make_float4(ch[t][0][2], ch[t][0][3], ch[t][1][2], ch[t][1][3]);
            if (cq == 0) {
                sigma_out[gr0] = softplus_dev(ch[t][2][0]);
                sigma_out[gr1] = softplus_dev(ch[t][2][2]);
            }
        }
    }
}

}  // namespace

extern "C" void kernel_launch(void* const* d_in, const int* in_sizes, int n_in,
                              void* d_out, int out_size) {
    const float* feat = (const float*)d_in[0];
    const float* W0   = (const float*)d_in[1];
    const float* b0   = (const float*)d_in[2];
    const float* W1   = (const float*)d_in[3];
    const float* b1   = (const float*)d_in[4];
    const float* Ws   = (const float*)d_in[5];
    const float* bs   = (const float*)d_in[6];
    const float* Wr   = (const float*)d_in[7];
    const float* br   = (const float*)d_in[8];

    float* out = (float*)d_out;
    const int Bn = in_sizes[0] / 32;           // rows (2^21)
    float* sigma = out;                         // [B]
    float* rgb   = out + Bn;                    // [B,16]

    const int rpc = Bn / NCTA;                  // 1024
    ngp_mlp_kernel<<<NCTA, CTA_THREADS>>>(feat, W0, b0, W1, b1, Ws, bs, Wr, br,
                                          sigma, rgb, rpc);
}

// round 15
// speedup vs baseline: 1.4280x; 1.0681x over previous
#include <cuda_runtime.h>
#include <cuda_fp16.h>
#include <cstdint>
#include <math.h>

// ---------------------------------------------------------------------------
// Portable tensor-core path: mma.sync + ldmatrix (no sm_103a-gated PTX).
// Round 12: R11 base + K-permuted W0 so feat is loaded with contiguous
// LDG.128 straight into A-fragment registers (wavefronts halved).
// ---------------------------------------------------------------------------

#define LDSM_X4(r0, r1, r2, r3, addr) \
    asm volatile("ldmatrix.sync.aligned.m8n8.x4.shared.b16 {%0,%1,%2,%3}, [%4];" \
                 : "=r"(r0), "=r"(r1), "=r"(r2), "=r"(r3) : "r"(addr))

#define LDSM_X2(r0, r1, addr) \
    asm volatile("ldmatrix.sync.aligned.m8n8.x2.shared.b16 {%0,%1}, [%2];" \
                 : "=r"(r0), "=r"(r1) : "r"(addr))

#define MMA16816(c, a0, a1, a2, a3, b0, b1) \
    asm volatile("mma.sync.aligned.m16n8k16.row.col.f32.f16.f16.f32 " \
                 "{%0,%1,%2,%3}, {%4,%5,%6,%7}, {%8,%9}, {%0,%1,%2,%3};" \
                 : "+f"((c)[0]), "+f"((c)[1]), "+f"((c)[2]), "+f"((c)[3]) \
                 : "r"(a0), "r"(a1), "r"(a2), "r"(a3), "r"(b0), "r"(b1))

namespace {

__device__ __forceinline__ uint32_t smem_u32(const void* p) {
    uint32_t a;
    asm("{ .reg .u64 t; cvta.to.shared.u64 t, %1; cvt.u32.u64 %0, t; }"
        : "=r"(a) : "l"(p));
    return a;
}

__device__ __forceinline__ uint32_t pack_f16x2(float lo, float hi) {
    uint32_t r;
    asm("cvt.rn.f16x2.f32 %0, %1, %2;" : "=r"(r) : "f"(hi), "f"(lo));
    return r;
}

__device__ __forceinline__ uint32_t pack_relu2(float lo, float hi) {
    uint32_t r = pack_f16x2(lo, hi);
    asm("max.f16x2 %0, %0, %1;" : "+r"(r) : "r"(0u));
    return r;
}

__device__ __forceinline__ float2 lds64(uint32_t addr) {
    float2 r;
    asm volatile("ld.shared.v2.f32 {%0,%1}, [%2];"
                 : "=f"(r.x), "=f"(r.y) : "r"(addr));
    return r;
}

__device__ __forceinline__ float softplus_dev(float s) {
    return (s > 20.0f) ? s : log1pf(expf(s));
}

constexpr int WSTR = 72;     // halfs per SMEM row (144B) -> ldmatrix conflict-free
constexpr int NCTA = 2048;
constexpr int CTA_THREADS = 128;

__global__ void __launch_bounds__(128, 4) ngp_mlp_kernel(
    const float* __restrict__ feat,
    const float* __restrict__ W0, const float* __restrict__ b0,
    const float* __restrict__ W1, const float* __restrict__ b1,
    const float* __restrict__ Ws, const float* __restrict__ bs,
    const float* __restrict__ Wr, const float* __restrict__ br,
    float* __restrict__ sigma_out, float* __restrict__ rgb_out,
    int rows_per_cta)
{
    __shared__ __half w0t[64 * WSTR];      // [n<64][perm k<32] fp16
    __shared__ __half w1t[64 * WSTR];      // [n<64][k<64]
    __shared__ __half w2t[24 * WSTR];      // permuted head: h<16 rgb, h=16 sigma
    __shared__ float  sbias[152];          // b0 | b1 | permuted head bias

    const int tid  = threadIdx.x;
    const int wid  = tid >> 5;
    const int lane = tid & 31;

    // ---- stage weights: fp32 gmem [K][N] -> fp16 smem [N][K] ----
    // W0: K-permuted so feat can be loaded as contiguous float4.
    // physical k = 16kt + 4cq + j  ->  logical l = 16kt + 2cq + (j&1) + 8(j>>1)
    for (int i = tid; i < 32 * 64; i += CTA_THREADS) {
        int k = i >> 6, n = i & 63;
        int l = (k & 16) + ((k >> 2) & 3) * 2 + (k & 1) + ((k >> 1) & 1) * 8;
        w0t[n * WSTR + l] = __float2half(W0[i]);
    }
    for (int i = tid; i < 64 * 64; i += CTA_THREADS) {
        int k = i >> 6, n = i & 63;
        w1t[n * WSTR + k] = __float2half(W1[i]);
    }
    for (int i = tid; i < 24 * WSTR; i += CTA_THREADS)
        w2t[i] = __float2half(0.0f);
    if (tid < 64) { sbias[tid] = b0[tid]; sbias[64 + tid] = b1[tid]; }
    if (tid < 24) {
        // permuted head bias: position h<16 <- br[4c+2n+j], h==16 <- bs-1
        float v = 0.0f;
        if (tid == 16) v = bs[0] - 1.0f;
        else if (tid < 16) {
            int n = tid >> 3, c = (tid >> 1) & 3, j = tid & 1;
            v = br[4 * c + 2 * n + j];
        }
        sbias[128 + tid] = v;
    }
    __syncthreads();
    if (tid < 64)
        w2t[16 * WSTR + tid] = __float2half(Ws[tid]);   // sigma at head col 16
    for (int i = tid; i < 64 * 16; i += CTA_THREADS) {   // rgb col g -> pos h
        int k = i >> 4, g = i & 15;
        int h = ((g >> 1) & 1) * 8 + (g >> 2) * 2 + (g & 1);
        w2t[h * WSTR + k] = __float2half(Wr[i]);
    }
    __syncthreads();

    // ---- addressing ----
    const uint32_t w0b = smem_u32(w0t), w1b = smem_u32(w1t), w2b = smem_u32(w2t);
    const uint32_t sb  = smem_u32(sbias);
    const int l15  = lane & 15;
    const int col2 = (lane & 3) * 2;
    const int cq   = lane & 3;

    const uint32_t bl4 = (uint32_t)((((lane >> 4) & 1) * 8 + (lane & 7)) * (WSTR * 2)
                                    + ((lane >> 3) & 1) * 16);
    const uint32_t bl2 = (uint32_t)((l15 & 7) * (WSTR * 2) + ((l15 >> 3) & 1) * 16);

    const int ep_row   = lane >> 2;          // A-fragment row within tile

    const uint32_t sb0 = sb + (uint32_t)col2 * 4;        // b0
    const uint32_t sb1 = sb0 + 256;                      // b1
    const uint32_t sbh = sb0 + 512;                      // head

    const int cta_base = blockIdx.x * rows_per_cta;
    const float4* f4 = (const float4*)feat;

    // prime pipeline: contiguous float4 feat loads (K-permuted fragment)
    // vf[t][h][kt]: tile t (rows +16t), row-half h (+8h), k-chunk kt
    float4 vf[2][2][2];
    {
        size_t rb = (size_t)(cta_base + wid * 32 + ep_row);
        #pragma unroll
        for (int t = 0; t < 2; t++)
            #pragma unroll
            for (int h = 0; h < 2; h++)
                #pragma unroll
                for (int kt = 0; kt < 2; kt++)
                    vf[t][h][kt] =
                        f4[(rb + (size_t)(t * 16 + h * 8)) * 8 + kt * 4 + cq];
    }

    #pragma unroll 1
    for (int it = 0; it < rows_per_cta; it += 128) {
        const int warp_r0 = cta_base + it + wid * 32;

        // -- convert prefetched feat to layer-0 A fragments (vf dies here) --
        // logical k slots: (x,y) -> {2cq, 2cq+1}, (z,w) -> {2cq+8, 2cq+9}
        uint32_t A0[2][2][4];
        #pragma unroll
        for (int t = 0; t < 2; t++)
            #pragma unroll
            for (int kt = 0; kt < 2; kt++)
                #pragma unroll
                for (int h = 0; h < 2; h++) {
                    A0[t][kt][h]     = pack_f16x2(vf[t][h][kt].x, vf[t][h][kt].y);
                    A0[t][kt][2 + h] = pack_f16x2(vf[t][h][kt].z, vf[t][h][kt].w);
                }

        // -- layer 0: [32,32] @ W0(permuted); B-fragments feed both tiles --
        float c[2][8][4];
        #pragma unroll
        for (int nt = 0; nt < 8; nt++) {
            float2 bv = lds64(sb0 + (uint32_t)nt * 32);
            #pragma unroll
            for (int t = 0; t < 2; t++) {
                c[t][nt][0] = bv.x; c[t][nt][1] = bv.y;
                c[t][nt][2] = bv.x; c[t][nt][3] = bv.y;
            }
        }
        #pragma unroll
        for (int kt = 0; kt < 2; kt++)
            #pragma unroll
            for (int np = 0; np < 8; np += 2) {
                uint32_t b0r, b1r, b2r, b3r;
                LDSM_X4(b0r, b1r, b2r, b3r,
                        w0b + bl4 + (uint32_t)np * (8 * WSTR * 2) + kt * 32);
                #pragma unroll
                for (int t = 0; t < 2; t++) {
                    MMA16816(c[t][np],     A0[t][kt][0], A0[t][kt][1],
                             A0[t][kt][2], A0[t][kt][3], b0r, b1r);
                    MMA16816(c[t][np + 1], A0[t][kt][0], A0[t][kt][1],
                             A0[t][kt][2], A0[t][kt][3], b2r, b3r);
                }
            }

        // -- repack C -> A (relu fused) --
        uint32_t A1[2][4][4];
        #pragma unroll
        for (int t = 0; t < 2; t++)
            #pragma unroll
            for (int kt = 0; kt < 4; kt++) {
                A1[t][kt][0] = pack_relu2(c[t][2 * kt][0],     c[t][2 * kt][1]);
                A1[t][kt][1] = pack_relu2(c[t][2 * kt][2],     c[t][2 * kt][3]);
                A1[t][kt][2] = pack_relu2(c[t][2 * kt + 1][0], c[t][2 * kt + 1][1]);
                A1[t][kt][3] = pack_relu2(c[t][2 * kt + 1][2], c[t][2 * kt + 1][3]);
            }

        // -- layer 1: [32,64] @ W1 --
        #pragma unroll
        for (int nt = 0; nt < 8; nt++) {
            float2 bv = lds64(sb1 + (uint32_t)nt * 32);
            #pragma unroll
            for (int t = 0; t < 2; t++) {
                c[t][nt][0] = bv.x; c[t][nt][1] = bv.y;
                c[t][nt][2] = bv.x; c[t][nt][3] = bv.y;
            }
        }
        #pragma unroll
        for (int kt = 0; kt < 4; kt++)
            #pragma unroll
            for (int np = 0; np < 8; np += 2) {
                uint32_t b0r, b1r, b2r, b3r;
                LDSM_X4(b0r, b1r, b2r, b3r,
                        w1b + bl4 + (uint32_t)np * (8 * WSTR * 2) + kt * 32);
                #pragma unroll
                for (int t = 0; t < 2; t++) {
                    MMA16816(c[t][np],     A1[t][kt][0], A1[t][kt][1],
                             A1[t][kt][2], A1[t][kt][3], b0r, b1r);
                    MMA16816(c[t][np + 1], A1[t][kt][0], A1[t][kt][1],
                             A1[t][kt][2], A1[t][kt][3], b2r, b3r);
                }
            }

        // -- LATE prefetch of next iteration's feat (vf live only from here) --
        {
            const int itn = (it + 128 < rows_per_cta) ? it + 128 : it;
            size_t rb = (size_t)(cta_base + itn + wid * 32 + ep_row);
            #pragma unroll
            for (int t = 0; t < 2; t++)
                #pragma unroll
                for (int h = 0; h < 2; h++)
                    #pragma unroll
                    for (int kt = 0; kt < 2; kt++)
                        vf[t][h][kt] =
                            f4[(rb + (size_t)(t * 16 + h * 8)) * 8 + kt * 4 + cq];
        }

        // -- repack again (reuse A1 storage) --
        #pragma unroll
        for (int t = 0; t < 2; t++)
            #pragma unroll
            for (int kt = 0; kt < 4; kt++) {
                A1[t][kt][0] = pack_relu2(c[t][2 * kt][0],     c[t][2 * kt][1]);
                A1[t][kt][1] = pack_relu2(c[t][2 * kt][2],     c[t][2 * kt][3]);
                A1[t][kt][2] = pack_relu2(c[t][2 * kt + 1][0], c[t][2 * kt + 1][1]);
                A1[t][kt][3] = pack_relu2(c[t][2 * kt + 1][2], c[t][2 * kt + 1][3]);
            }

        // -- heads (permuted): [32,64] @ W2 -> thread owns rgb quad --
        float ch[2][3][4];
        #pragma unroll
        for (int nt = 0; nt < 3; nt++) {
            float2 bv = lds64(sbh + (uint32_t)nt * 32);
            #pragma unroll
            for (int t = 0; t < 2; t++) {
                ch[t][nt][0] = bv.x; ch[t][nt][1] = bv.y;
                ch[t][nt][2] = bv.x; ch[t][nt][3] = bv.y;
            }
        }
        #pragma unroll
        for (int kt = 0; kt < 4; kt++) {
            uint32_t b0r, b1r, b2r, b3r;
            LDSM_X4(b0r, b1r, b2r, b3r, w2b + bl4 + kt * 32);
            uint32_t d0r, d1r;
            LDSM_X2(d0r, d1r, w2b + bl2 + (uint32_t)(16 * WSTR * 2) + kt * 32);
            #pragma unroll
            for (int t = 0; t < 2; t++) {
                MMA16816(ch[t][0], A1[t][kt][0], A1[t][kt][1],
                         A1[t][kt][2], A1[t][kt][3], b0r, b1r);
                MMA16816(ch[t][1], A1[t][kt][0], A1[t][kt][1],
                         A1[t][kt][2], A1[t][kt][3], b2r, b3r);
                MMA16816(ch[t][2], A1[t][kt][0], A1[t][kt][1],
                         A1[t][kt][2], A1[t][kt][3], d0r, d1r);
            }
        }

        // -- epilogue: fully coalesced stores --
        #pragma unroll
        for (int t = 0; t < 2; t++) {
            const int gr0 = warp_r0 + t * 16 + ep_row;
            const int gr1 = gr0 + 8;
            *(float4*)(rgb_out + (size_t)gr0 * 16 + 4 * cq) =
                make_float4(ch[t][0][0], ch[t][0][1], ch[t][1][0], ch[t][1][1]);
            *(float4*)(rgb_out + (size_t)gr1 * 16 + 4 * cq) =
                make_float4(ch[t][0][2], ch[t][0][3], ch[t][1][2], ch[t][1][3]);
            if (cq == 0) {
                sigma_out[gr0] = softplus_dev(ch[t][2][0]);
                sigma_out[gr1] = softplus_dev(ch[t][2][2]);
            }
        }
    }
}

}  // namespace

extern "C" void kernel_launch(void* const* d_in, const int* in_sizes, int n_in,
                              void* d_out, int out_size) {
    const float* feat = (const float*)d_in[0];
    const float* W0   = (const float*)d_in[1];
    const float* b0   = (const float*)d_in[2];
    const float* W1   = (const float*)d_in[3];
    const float* b1   = (const float*)d_in[4];
    const float* Ws   = (const float*)d_in[5];
    const float* bs   = (const float*)d_in[6];
    const float* Wr   = (const float*)d_in[7];
    const float* br   = (const float*)d_in[8];

    float* out = (float*)d_out;
    const int Bn = in_sizes[0] / 32;           // rows (2^21)
    float* sigma = out;                         // [B]
    float* rgb   = out + Bn;                    // [B,16]

    const int rpc = Bn / NCTA;                  // 1024
    ngp_mlp_kernel<<<NCTA, CTA_THREADS>>>(feat, W0, b0, W1, b1, Ws, bs, Wr, br,
                                          sigma, rgb, rpc);
}

// round 16
// speedup vs baseline: 1.5504x; 1.0857x over previous
#include <cuda_runtime.h>
#include <cuda_fp16.h>
#include <cstdint>
#include <math.h>

// ---------------------------------------------------------------------------
// Portable tensor-core path: mma.sync + ldmatrix (no sm_103a-gated PTX).
// Round 16: R12 body (K-permuted W0 -> LDG.128 feat-to-fragment, permuted
// head -> coalesced STG.128 epilogue, 4 CTAs/SM) + PERSISTENT grid-stride
// CTAs (608 = 152 SMs x 4) to kill the fractional-wave tail and cut weight
// staging from 2048x to 608x.
// ---------------------------------------------------------------------------

#define LDSM_X4(r0, r1, r2, r3, addr) \
    asm volatile("ldmatrix.sync.aligned.m8n8.x4.shared.b16 {%0,%1,%2,%3}, [%4];" \
                 : "=r"(r0), "=r"(r1), "=r"(r2), "=r"(r3) : "r"(addr))

#define LDSM_X2(r0, r1, addr) \
    asm volatile("ldmatrix.sync.aligned.m8n8.x2.shared.b16 {%0,%1}, [%2];" \
                 : "=r"(r0), "=r"(r1) : "r"(addr))

#define MMA16816(c, a0, a1, a2, a3, b0, b1) \
    asm volatile("mma.sync.aligned.m16n8k16.row.col.f32.f16.f16.f32 " \
                 "{%0,%1,%2,%3}, {%4,%5,%6,%7}, {%8,%9}, {%0,%1,%2,%3};" \
                 : "+f"((c)[0]), "+f"((c)[1]), "+f"((c)[2]), "+f"((c)[3]) \
                 : "r"(a0), "r"(a1), "r"(a2), "r"(a3), "r"(b0), "r"(b1))

namespace {

__device__ __forceinline__ uint32_t smem_u32(const void* p) {
    uint32_t a;
    asm("{ .reg .u64 t; cvta.to.shared.u64 t, %1; cvt.u32.u64 %0, t; }"
        : "=r"(a) : "l"(p));
    return a;
}

__device__ __forceinline__ uint32_t pack_f16x2(float lo, float hi) {
    uint32_t r;
    asm("cvt.rn.f16x2.f32 %0, %1, %2;" : "=r"(r) : "f"(hi), "f"(lo));
    return r;
}

__device__ __forceinline__ uint32_t pack_relu2(float lo, float hi) {
    uint32_t r = pack_f16x2(lo, hi);
    asm("max.f16x2 %0, %0, %1;" : "+r"(r) : "r"(0u));
    return r;
}

__device__ __forceinline__ float2 lds64(uint32_t addr) {
    float2 r;
    asm volatile("ld.shared.v2.f32 {%0,%1}, [%2];"
                 : "=f"(r.x), "=f"(r.y) : "r"(addr));
    return r;
}

__device__ __forceinline__ float softplus_dev(float s) {
    return (s > 20.0f) ? s : log1pf(expf(s));
}

constexpr int WSTR = 72;     // halfs per SMEM row (144B) -> ldmatrix conflict-free
constexpr int CTA_THREADS = 128;
constexpr int GRID = 608;    // 152 SMs x 4 CTAs/SM, all resident from wave 1

__global__ void __launch_bounds__(128, 4) ngp_mlp_kernel(
    const float* __restrict__ feat,
    const float* __restrict__ W0, const float* __restrict__ b0,
    const float* __restrict__ W1, const float* __restrict__ b1,
    const float* __restrict__ Ws, const float* __restrict__ bs,
    const float* __restrict__ Wr, const float* __restrict__ br,
    float* __restrict__ sigma_out, float* __restrict__ rgb_out,
    int nchunks)        // total 128-row chunks
{
    __shared__ __half w0t[64 * WSTR];      // [n<64][perm k<32] fp16
    __shared__ __half w1t[64 * WSTR];      // [n<64][k<64]
    __shared__ __half w2t[24 * WSTR];      // permuted head: h<16 rgb, h=16 sigma
    __shared__ float  sbias[152];          // b0 | b1 | permuted head bias

    const int tid  = threadIdx.x;
    const int wid  = tid >> 5;
    const int lane = tid & 31;

    // ---- stage weights: fp32 gmem [K][N] -> fp16 smem [N][K] ----
    // W0: K-permuted so feat can be loaded as contiguous float4.
    // physical k = 16kt + 4cq + j  ->  logical l = 16kt + 2cq + (j&1) + 8(j>>1)
    for (int i = tid; i < 32 * 64; i += CTA_THREADS) {
        int k = i >> 6, n = i & 63;
        int l = (k & 16) + ((k >> 2) & 3) * 2 + (k & 1) + ((k >> 1) & 1) * 8;
        w0t[n * WSTR + l] = __float2half(W0[i]);
    }
    for (int i = tid; i < 64 * 64; i += CTA_THREADS) {
        int k = i >> 6, n = i & 63;
        w1t[n * WSTR + k] = __float2half(W1[i]);
    }
    for (int i = tid; i < 24 * WSTR; i += CTA_THREADS)
        w2t[i] = __float2half(0.0f);
    if (tid < 64) { sbias[tid] = b0[tid]; sbias[64 + tid] = b1[tid]; }
    if (tid < 24) {
        // permuted head bias: position h<16 <- br[4c+2n+j], h==16 <- bs-1
        float v = 0.0f;
        if (tid == 16) v = bs[0] - 1.0f;
        else if (tid < 16) {
            int n = tid >> 3, c = (tid >> 1) & 3, j = tid & 1;
            v = br[4 * c + 2 * n + j];
        }
        sbias[128 + tid] = v;
    }
    __syncthreads();
    if (tid < 64)
        w2t[16 * WSTR + tid] = __float2half(Ws[tid]);   // sigma at head col 16
    for (int i = tid; i < 64 * 16; i += CTA_THREADS) {   // rgb col g -> pos h
        int k = i >> 4, g = i & 15;
        int h = ((g >> 1) & 1) * 8 + (g >> 2) * 2 + (g & 1);
        w2t[h * WSTR + k] = __float2half(Wr[i]);
    }
    __syncthreads();

    // ---- addressing ----
    const uint32_t w0b = smem_u32(w0t), w1b = smem_u32(w1t), w2b = smem_u32(w2t);
    const uint32_t sb  = smem_u32(sbias);
    const int l15  = lane & 15;
    const int col2 = (lane & 3) * 2;
    const int cq   = lane & 3;

    const uint32_t bl4 = (uint32_t)((((lane >> 4) & 1) * 8 + (lane & 7)) * (WSTR * 2)
                                    + ((lane >> 3) & 1) * 16);
    const uint32_t bl2 = (uint32_t)((l15 & 7) * (WSTR * 2) + ((l15 >> 3) & 1) * 16);

    const int ep_row   = lane >> 2;          // A-fragment row within tile

    const uint32_t sb0 = sb + (uint32_t)col2 * 4;        // b0
    const uint32_t sb1 = sb0 + 256;                      // b1
    const uint32_t sbh = sb0 + 512;                      // head

    const float4* f4 = (const float4*)feat;

    // ---- persistent grid-stride loop over 128-row chunks ----
    int chunk = blockIdx.x;
    if (chunk >= nchunks) return;

    // prime pipeline: contiguous float4 feat loads for first chunk
    float4 vf[2][2][2];
    {
        size_t rb = (size_t)chunk * 128 + (size_t)(wid * 32 + ep_row);
        #pragma unroll
        for (int t = 0; t < 2; t++)
            #pragma unroll
            for (int h = 0; h < 2; h++)
                #pragma unroll
                for (int kt = 0; kt < 2; kt++)
                    vf[t][h][kt] =
                        f4[(rb + (size_t)(t * 16 + h * 8)) * 8 + kt * 4 + cq];
    }

    #pragma unroll 1
    for (; chunk < nchunks; chunk += GRID) {
        const int warp_r0 = chunk * 128 + wid * 32;

        // -- convert prefetched feat to layer-0 A fragments (vf dies here) --
        uint32_t A0[2][2][4];
        #pragma unroll
        for (int t = 0; t < 2; t++)
            #pragma unroll
            for (int kt = 0; kt < 2; kt++)
                #pragma unroll
                for (int h = 0; h < 2; h++) {
                    A0[t][kt][h]     = pack_f16x2(vf[t][h][kt].x, vf[t][h][kt].y);
                    A0[t][kt][2 + h] = pack_f16x2(vf[t][h][kt].z, vf[t][h][kt].w);
                }

        // -- layer 0: [32,32] @ W0(permuted); B-fragments feed both tiles --
        float c[2][8][4];
        #pragma unroll
        for (int nt = 0; nt < 8; nt++) {
            float2 bv = lds64(sb0 + (uint32_t)nt * 32);
            #pragma unroll
            for (int t = 0; t < 2; t++) {
                c[t][nt][0] = bv.x; c[t][nt][1] = bv.y;
                c[t][nt][2] = bv.x; c[t][nt][3] = bv.y;
            }
        }
        #pragma unroll
        for (int kt = 0; kt < 2; kt++)
            #pragma unroll
            for (int np = 0; np < 8; np += 2) {
                uint32_t b0r, b1r, b2r, b3r;
                LDSM_X4(b0r, b1r, b2r, b3r,
                        w0b + bl4 + (uint32_t)np * (8 * WSTR * 2) + kt * 32);
                #pragma unroll
                for (int t = 0; t < 2; t++) {
                    MMA16816(c[t][np],     A0[t][kt][0], A0[t][kt][1],
                             A0[t][kt][2], A0[t][kt][3], b0r, b1r);
                    MMA16816(c[t][np + 1], A0[t][kt][0], A0[t][kt][1],
                             A0[t][kt][2], A0[t][kt][3], b2r, b3r);
                }
            }

        // -- repack C -> A (relu fused) --
        uint32_t A1[2][4][4];
        #pragma unroll
        for (int t = 0; t < 2; t++)
            #pragma unroll
            for (int kt = 0; kt < 4; kt++) {
                A1[t][kt][0] = pack_relu2(c[t][2 * kt][0],     c[t][2 * kt][1]);
                A1[t][kt][1] = pack_relu2(c[t][2 * kt][2],     c[t][2 * kt][3]);
                A1[t][kt][2] = pack_relu2(c[t][2 * kt + 1][0], c[t][2 * kt + 1][1]);
                A1[t][kt][3] = pack_relu2(c[t][2 * kt + 1][2], c[t][2 * kt + 1][3]);
            }

        // -- layer 1: [32,64] @ W1 --
        #pragma unroll
        for (int nt = 0; nt < 8; nt++) {
            float2 bv = lds64(sb1 + (uint32_t)nt * 32);
            #pragma unroll
            for (int t = 0; t < 2; t++) {
                c[t][nt][0] = bv.x; c[t][nt][1] = bv.y;
                c[t][nt][2] = bv.x; c[t][nt][3] = bv.y;
            }
        }
        #pragma unroll
        for (int kt = 0; kt < 4; kt++)
            #pragma unroll
            for (int np = 0; np < 8; np += 2) {
                uint32_t b0r, b1r, b2r, b3r;
                LDSM_X4(b0r, b1r, b2r, b3r,
                        w1b + bl4 + (uint32_t)np * (8 * WSTR * 2) + kt * 32);
                #pragma unroll
                for (int t = 0; t < 2; t++) {
                    MMA16816(c[t][np],     A1[t][kt][0], A1[t][kt][1],
                             A1[t][kt][2], A1[t][kt][3], b0r, b1r);
                    MMA16816(c[t][np + 1], A1[t][kt][0], A1[t][kt][1],
                             A1[t][kt][2], A1[t][kt][3], b2r, b3r);
                }
            }

        // -- LATE prefetch of next chunk's feat (vf live only from here) --
        {
            const int cn = (chunk + GRID < nchunks) ? chunk + GRID : chunk;
            size_t rb = (size_t)cn * 128 + (size_t)(wid * 32 + ep_row);
            #pragma unroll
            for (int t = 0; t < 2; t++)
                #pragma unroll
                for (int h = 0; h < 2; h++)
                    #pragma unroll
                    for (int kt = 0; kt < 2; kt++)
                        vf[t][h][kt] =
                            f4[(rb + (size_t)(t * 16 + h * 8)) * 8 + kt * 4 + cq];
        }

        // -- repack again (reuse A1 storage) --
        #pragma unroll
        for (int t = 0; t < 2; t++)
            #pragma unroll
            for (int kt = 0; kt < 4; kt++) {
                A1[t][kt][0] = pack_relu2(c[t][2 * kt][0],     c[t][2 * kt][1]);
                A1[t][kt][1] = pack_relu2(c[t][2 * kt][2],     c[t][2 * kt][3]);
                A1[t][kt][2] = pack_relu2(c[t][2 * kt + 1][0], c[t][2 * kt + 1][1]);
                A1[t][kt][3] = pack_relu2(c[t][2 * kt + 1][2], c[t][2 * kt + 1][3]);
            }

        // -- heads (permuted): [32,64] @ W2 -> thread owns rgb quad --
        float ch[2][3][4];
        #pragma unroll
        for (int nt = 0; nt < 3; nt++) {
            float2 bv = lds64(sbh + (uint32_t)nt * 32);
            #pragma unroll
            for (int t = 0; t < 2; t++) {
                ch[t][nt][0] = bv.x; ch[t][nt][1] = bv.y;
                ch[t][nt][2] = bv.x; ch[t][nt][3] = bv.y;
            }
        }
        #pragma unroll
        for (int kt = 0; kt < 4; kt++) {
            uint32_t b0r, b1r, b2r, b3r;
            LDSM_X4(b0r, b1r, b2r, b3r, w2b + bl4 + kt * 32);
            uint32_t d0r, d1r;
            LDSM_X2(d0r, d1r, w2b + bl2 + (uint32_t)(16 * WSTR * 2) + kt * 32);
            #pragma unroll
            for (int t = 0; t < 2; t++) {
                MMA16816(ch[t][0], A1[t][kt][0], A1[t][kt][1],
                         A1[t][kt][2], A1[t][kt][3], b0r, b1r);
                MMA16816(ch[t][1], A1[t][kt][0], A1[t][kt][1],
                         A1[t][kt][2], A1[t][kt][3], b2r, b3r);
                MMA16816(ch[t][2], A1[t][kt][0], A1[t][kt][1],
                         A1[t][kt][2], A1[t][kt][3], d0r, d1r);
            }
        }

        // -- epilogue: fully coalesced stores --
        #pragma unroll
        for (int t = 0; t < 2; t++) {
            const int gr0 = warp_r0 + t * 16 + ep_row;
            const int gr1 = gr0 + 8;
            *(float4*)(rgb_out + (size_t)gr0 * 16 + 4 * cq) =
                make_float4(ch[t][0][0], ch[t][0][1], ch[t][1][0], ch[t][1][1]);
            *(float4*)(rgb_out + (size_t)gr1 * 16 + 4 * cq) =
                make_float4(ch[t][0][2], ch[t][0][3], ch[t][1][2], ch[t][1][3]);
            if (cq == 0) {
                sigma_out[gr0] = softplus_dev(ch[t][2][0]);
                sigma_out[gr1] = softplus_dev(ch[t][2][2]);
            }
        }
    }
}

}  // namespace

extern "C" void kernel_launch(void* const* d_in, const int* in_sizes, int n_in,
                              void* d_out, int out_size) {
    const float* feat = (const float*)d_in[0];
    const float* W0   = (const float*)d_in[1];
    const float* b0   = (const float*)d_in[2];
    const float* W1   = (const float*)d_in[3];
    const float* b1   = (const float*)d_in[4];
    const float* Ws   = (const float*)d_in[5];
    const float* bs   = (const float*)d_in[6];
    const float* Wr   = (const float*)d_in[7];
    const float* br   = (const float*)d_in[8];

    float* out = (float*)d_out;
    const int Bn = in_sizes[0] / 32;           // rows (2^21)
    float* sigma = out;                         // [B]
    float* rgb   = out + Bn;                    // [B,16]

    const int nchunks = Bn / 128;               // 16384
    const int grid = (nchunks < GRID) ? nchunks : GRID;
    ngp_mlp_kernel<<<grid, CTA_THREADS>>>(feat, W0, b0, W1, b1, Ws, bs, Wr, br,
                                          sigma, rgb, nchunks);
}